// round 9
// baseline (speedup 1.0000x reference)
#include <cuda_runtime.h>
#include <cuda_bf16.h>

// y = 0.75 * x @ colsum(W)
// x: [M,K] fp32 row-major, W: [N,K] fp32 row-major, out: [M,1] fp32
// M = K = N = 8192.
//
// Pipelined: K split in halves. colsumA -> (rowdotA || colsumB) -> rowdotB.
// Fork/join via event pattern so the captured graph has parallel branches.

#define M_DIM 8192
#define K_DIM 8192
#define N_DIM 8192
#define K_HALF (K_DIM / 2)          // 4096
#define K_HALF4 (K_HALF / 4)        // 1024 float4

// Scratch (no allocations allowed): column sums + rowdot partials.
__device__ float g_wcs[K_DIM];
__device__ float g_ypart[M_DIM];

// ---------------------------------------------------------------------------
// Column-sum of one K-half of W.
// Grid (K_HALF4/256, 128) = (4,128) -> 512 blocks. Each thread owns one
// float4 column group in [k0, k0+K_HALF), accumulates 64 rows with 8-deep
// load batching into 4 independent accumulators, then 4 atomicAdds.
// ---------------------------------------------------------------------------
#define CS_THREADS 256
#define CS_ROW_SPLITS 128
#define CS_ROWS (N_DIM / CS_ROW_SPLITS)   // 64

__global__ __launch_bounds__(CS_THREADS)
void colsum_kernel(const float* __restrict__ W, int k0_4) {
    const int col4 = k0_4 + blockIdx.x * CS_THREADS + threadIdx.x;
    const int r0 = blockIdx.y * CS_ROWS;
    const float4* __restrict__ Wv = reinterpret_cast<const float4*>(W);
    const long long ld4 = K_DIM / 4;

    float4 a0 = make_float4(0.f, 0.f, 0.f, 0.f);
    float4 a1 = make_float4(0.f, 0.f, 0.f, 0.f);
    float4 a2 = make_float4(0.f, 0.f, 0.f, 0.f);
    float4 a3 = make_float4(0.f, 0.f, 0.f, 0.f);

    const float4* p = &Wv[(long long)r0 * ld4 + col4];

#pragma unroll 2
    for (int r = 0; r < CS_ROWS; r += 8) {
        float4 v0 = __ldcs(p + 0 * ld4);
        float4 v1 = __ldcs(p + 1 * ld4);
        float4 v2 = __ldcs(p + 2 * ld4);
        float4 v3 = __ldcs(p + 3 * ld4);
        float4 v4 = __ldcs(p + 4 * ld4);
        float4 v5 = __ldcs(p + 5 * ld4);
        float4 v6 = __ldcs(p + 6 * ld4);
        float4 v7 = __ldcs(p + 7 * ld4);
        p += 8 * ld4;
        a0.x += v0.x; a0.y += v0.y; a0.z += v0.z; a0.w += v0.w;
        a1.x += v1.x; a1.y += v1.y; a1.z += v1.z; a1.w += v1.w;
        a2.x += v2.x; a2.y += v2.y; a2.z += v2.z; a2.w += v2.w;
        a3.x += v3.x; a3.y += v3.y; a3.z += v3.z; a3.w += v3.w;
        a0.x += v4.x; a0.y += v4.y; a0.z += v4.z; a0.w += v4.w;
        a1.x += v5.x; a1.y += v5.y; a1.z += v5.z; a1.w += v5.w;
        a2.x += v6.x; a2.y += v6.y; a2.z += v6.z; a2.w += v6.w;
        a3.x += v7.x; a3.y += v7.y; a3.z += v7.z; a3.w += v7.w;
    }

    float4 acc;
    acc.x = (a0.x + a1.x) + (a2.x + a3.x);
    acc.y = (a0.y + a1.y) + (a2.y + a3.y);
    acc.z = (a0.z + a1.z) + (a2.z + a3.z);
    acc.w = (a0.w + a1.w) + (a2.w + a3.w);

    float* dst = &g_wcs[col4 * 4];
    atomicAdd(dst + 0, acc.x);
    atomicAdd(dst + 1, acc.y);
    atomicAdd(dst + 2, acc.z);
    atomicAdd(dst + 3, acc.w);
}

// ---------------------------------------------------------------------------
// Per-row partial dot over one K-half. 2 rows per block, interleaved so each
// wcs load feeds two FFMA chains (the best-measured rowdot shape: regs ~38,
// occ ~72%). FINAL=false: write partial to g_ypart. FINAL=true: add g_ypart,
// scale, write y.
// ---------------------------------------------------------------------------
#define RD_THREADS 256

template <bool FINAL>
__global__ __launch_bounds__(RD_THREADS)
void rowdot_kernel(const float* __restrict__ x, float* __restrict__ y, int k0_4) {
    const float4* __restrict__ wv = reinterpret_cast<const float4*>(g_wcs);
    __shared__ float warp_sums[2][RD_THREADS / 32];

    const int m0 = blockIdx.x * 2;
    const float4* __restrict__ xv0 =
        reinterpret_cast<const float4*>(x + (long long)m0 * K_DIM) + k0_4;
    const float4* __restrict__ xv1 =
        reinterpret_cast<const float4*>(x + (long long)(m0 + 1) * K_DIM) + k0_4;
    const float4* __restrict__ wvc = wv + k0_4;

    float acc0 = 0.0f, acc1 = 0.0f;
    // K_HALF4 = 1024 float4 per row-half; 256 threads -> 4 iterations each.
#pragma unroll
    for (int i = threadIdx.x; i < K_HALF4; i += RD_THREADS) {
        float4 b = __ldg(&wvc[i]);
        float4 p = __ldcs(&xv0[i]);
        float4 q = __ldcs(&xv1[i]);
        acc0 += p.x * b.x + p.y * b.y + p.z * b.z + p.w * b.w;
        acc1 += q.x * b.x + q.y * b.y + q.z * b.z + q.w * b.w;
    }

#pragma unroll
    for (int off = 16; off > 0; off >>= 1) {
        acc0 += __shfl_down_sync(0xFFFFFFFFu, acc0, off);
        acc1 += __shfl_down_sync(0xFFFFFFFFu, acc1, off);
    }

    if ((threadIdx.x & 31) == 0) {
        warp_sums[0][threadIdx.x >> 5] = acc0;
        warp_sums[1][threadIdx.x >> 5] = acc1;
    }
    __syncthreads();

    const int wid = threadIdx.x >> 5;
    const int lid = threadIdx.x & 31;
    if (wid < 2) {
        float v = (lid < RD_THREADS / 32) ? warp_sums[wid][lid] : 0.0f;
#pragma unroll
        for (int off = 4; off > 0; off >>= 1)
            v += __shfl_down_sync(0xFFFFFFFFu, v, off);
        if (lid == 0) {
            if (FINAL)
                y[m0 + wid] = 0.75f * (v + g_ypart[m0 + wid]);
            else
                g_ypart[m0 + wid] = v;
        }
    }
}

// ---------------------------------------------------------------------------
// Launch: forked-stream pipeline, capture-legal event pattern.
//   s0(default): memset, colsumA, [rec evA], colsumB, [wait evRA], rowdotB
//   s1(side)   : [wait evA], rowdotA, [rec evRA]
// ---------------------------------------------------------------------------
extern "C" void kernel_launch(void* const* d_in, const int* in_sizes, int n_in,
                              void* d_out, int out_size) {
    const float* x = (const float*)d_in[0];      // [M, K]
    const float* W = (const float*)d_in[1];      // [N, K]
    float* y = (float*)d_out;                    // [M, 1]

    // Few calls total (correctness + capture); fresh handles are cheap and
    // keep kernel_launch stateless.
    cudaStream_t s1;
    cudaStreamCreateWithFlags(&s1, cudaStreamNonBlocking);
    cudaEvent_t evA, evRA;
    cudaEventCreateWithFlags(&evA, cudaEventDisableTiming);
    cudaEventCreateWithFlags(&evRA, cudaEventDisableTiming);

    void* wcs_ptr = nullptr;
    cudaGetSymbolAddress(&wcs_ptr, g_wcs);
    cudaMemsetAsync(wcs_ptr, 0, K_DIM * sizeof(float));

    dim3 cs_grid(K_HALF4 / CS_THREADS, CS_ROW_SPLITS);   // (4, 128)

    // colsum of K-half A
    colsum_kernel<<<cs_grid, CS_THREADS>>>(W, 0);
    cudaEventRecord(evA, 0);

    // side stream: rowdot partial over half A (concurrent with colsumB)
    cudaStreamWaitEvent(s1, evA, 0);
    rowdot_kernel<false><<<M_DIM / 2, RD_THREADS, 0, s1>>>(x, y, 0);
    cudaEventRecord(evRA, s1);

    // main stream: colsum of K-half B
    colsum_kernel<<<cs_grid, CS_THREADS>>>(W, K_HALF4);

    // join, then final rowdot over half B
    cudaStreamWaitEvent(0, evRA, 0);
    rowdot_kernel<true><<<M_DIM / 2, RD_THREADS>>>(x, y, K_HALF4);

    cudaStreamDestroy(s1);
    cudaEventDestroy(evA);
    cudaEventDestroy(evRA);
}

// round 14
// speedup vs baseline: 1.1568x; 1.1568x over previous
#include <cuda_runtime.h>
#include <cuda_bf16.h>

// y = 0.75 * x @ colsum(W)
// x: [M,K] fp32 row-major, W: [N,K] fp32 row-major, out: [M,1] fp32
// M = K = N = 8192.
//
// Two streaming kernels, best-measured shapes from R2-R4:
//   colsum: R4 shape (~41.5us derived), rowdot: R2 shape (43.7us measured).

#define M_DIM 8192
#define K_DIM 8192
#define N_DIM 8192

// Scratch: column sums of W. __device__ global (no allocations allowed).
__device__ float g_wcs[K_DIM];

// ---------------------------------------------------------------------------
// Kernel 1: column-sum of W. (R4 best-measured variant)
// Grid: (8, 64). Each thread owns one float4 column group, accumulates 128
// rows with 8-deep load batching into 4 independent accumulators, then 4
// atomicAdds into g_wcs.
// ---------------------------------------------------------------------------
#define CS_THREADS 256
#define ROW_SPLITS 64
#define ROWS_PER_SPLIT (N_DIM / ROW_SPLITS)   // 128

__global__ __launch_bounds__(CS_THREADS)
void colsum_kernel(const float* __restrict__ W) {
    const int col4 = blockIdx.x * CS_THREADS + threadIdx.x;  // float4 index
    const int r0 = blockIdx.y * ROWS_PER_SPLIT;
    const float4* __restrict__ Wv = reinterpret_cast<const float4*>(W);
    const long long ld4 = K_DIM / 4;

    float4 a0 = make_float4(0.f, 0.f, 0.f, 0.f);
    float4 a1 = make_float4(0.f, 0.f, 0.f, 0.f);
    float4 a2 = make_float4(0.f, 0.f, 0.f, 0.f);
    float4 a3 = make_float4(0.f, 0.f, 0.f, 0.f);

    const float4* p = &Wv[(long long)r0 * ld4 + col4];

#pragma unroll 2
    for (int r = 0; r < ROWS_PER_SPLIT; r += 8) {
        float4 v0 = __ldcs(p + 0 * ld4);
        float4 v1 = __ldcs(p + 1 * ld4);
        float4 v2 = __ldcs(p + 2 * ld4);
        float4 v3 = __ldcs(p + 3 * ld4);
        float4 v4 = __ldcs(p + 4 * ld4);
        float4 v5 = __ldcs(p + 5 * ld4);
        float4 v6 = __ldcs(p + 6 * ld4);
        float4 v7 = __ldcs(p + 7 * ld4);
        p += 8 * ld4;
        a0.x += v0.x; a0.y += v0.y; a0.z += v0.z; a0.w += v0.w;
        a1.x += v1.x; a1.y += v1.y; a1.z += v1.z; a1.w += v1.w;
        a2.x += v2.x; a2.y += v2.y; a2.z += v2.z; a2.w += v2.w;
        a3.x += v3.x; a3.y += v3.y; a3.z += v3.z; a3.w += v3.w;
        a0.x += v4.x; a0.y += v4.y; a0.z += v4.z; a0.w += v4.w;
        a1.x += v5.x; a1.y += v5.y; a1.z += v5.z; a1.w += v5.w;
        a2.x += v6.x; a2.y += v6.y; a2.z += v6.z; a2.w += v6.w;
        a3.x += v7.x; a3.y += v7.y; a3.z += v7.z; a3.w += v7.w;
    }

    float4 acc;
    acc.x = (a0.x + a1.x) + (a2.x + a3.x);
    acc.y = (a0.y + a1.y) + (a2.y + a3.y);
    acc.z = (a0.z + a1.z) + (a2.z + a3.z);
    acc.w = (a0.w + a1.w) + (a2.w + a3.w);

    float* dst = &g_wcs[col4 * 4];
    atomicAdd(dst + 0, acc.x);
    atomicAdd(dst + 1, acc.y);
    atomicAdd(dst + 2, acc.z);
    atomicAdd(dst + 3, acc.w);
}

// ---------------------------------------------------------------------------
// Kernel 2: per-row dot product against g_wcs (L2-resident). (R2 best-
// measured variant: 43.7us, DRAM 78.5%, occ 71.7%)
// Grid 4096, 2 rows per block interleaved in one loop so each wcs load
// feeds two independent FFMA chains; full unroll -> 16+ loads in flight.
// ---------------------------------------------------------------------------
#define RD_THREADS 256
#define ROWS_PER_BLOCK 2

__global__ __launch_bounds__(RD_THREADS)
void rowdot_kernel(const float* __restrict__ x, float* __restrict__ y) {
    const float4* __restrict__ wv = reinterpret_cast<const float4*>(g_wcs);
    __shared__ float warp_sums[ROWS_PER_BLOCK][RD_THREADS / 32];

    const int m0 = blockIdx.x * ROWS_PER_BLOCK;
    const float4* __restrict__ xv0 =
        reinterpret_cast<const float4*>(x + (long long)m0 * K_DIM);
    const float4* __restrict__ xv1 =
        reinterpret_cast<const float4*>(x + (long long)(m0 + 1) * K_DIM);

    float acc0 = 0.0f, acc1 = 0.0f;
    // K/4 = 2048 float4 per row; 256 threads -> 8 iterations each.
#pragma unroll
    for (int i = threadIdx.x; i < K_DIM / 4; i += RD_THREADS) {
        float4 b = __ldg(&wv[i]);
        float4 p = __ldcs(&xv0[i]);
        float4 q = __ldcs(&xv1[i]);
        acc0 += p.x * b.x + p.y * b.y + p.z * b.z + p.w * b.w;
        acc1 += q.x * b.x + q.y * b.y + q.z * b.z + q.w * b.w;
    }

#pragma unroll
    for (int off = 16; off > 0; off >>= 1) {
        acc0 += __shfl_down_sync(0xFFFFFFFFu, acc0, off);
        acc1 += __shfl_down_sync(0xFFFFFFFFu, acc1, off);
    }

    if ((threadIdx.x & 31) == 0) {
        warp_sums[0][threadIdx.x >> 5] = acc0;
        warp_sums[1][threadIdx.x >> 5] = acc1;
    }
    __syncthreads();

    // First ROWS_PER_BLOCK warps each finish one row (8 partials each).
    const int wid = threadIdx.x >> 5;
    const int lid = threadIdx.x & 31;
    if (wid < ROWS_PER_BLOCK) {
        float v = (lid < RD_THREADS / 32) ? warp_sums[wid][lid] : 0.0f;
#pragma unroll
        for (int off = 4; off > 0; off >>= 1)
            v += __shfl_down_sync(0xFFFFFFFFu, v, off);
        if (lid == 0) y[m0 + wid] = 0.75f * v;
    }
}

// ---------------------------------------------------------------------------
// Launch. g_wcs zeroed via memset node (capturable, no kernel).
// ---------------------------------------------------------------------------
extern "C" void kernel_launch(void* const* d_in, const int* in_sizes, int n_in,
                              void* d_out, int out_size) {
    const float* x = (const float*)d_in[0];      // [M, K]
    const float* W = (const float*)d_in[1];      // [N, K]
    float* y = (float*)d_out;                    // [M, 1]

    void* wcs_ptr = nullptr;
    cudaGetSymbolAddress(&wcs_ptr, g_wcs);
    cudaMemsetAsync(wcs_ptr, 0, K_DIM * sizeof(float));

    dim3 cs_grid(K_DIM / 4 / CS_THREADS, ROW_SPLITS);  // (8, 64)
    colsum_kernel<<<cs_grid, CS_THREADS>>>(W);

    rowdot_kernel<<<M_DIM / ROWS_PER_BLOCK, RD_THREADS>>>(x, y);
}